// round 10
// baseline (speedup 1.0000x reference)
#include <cuda_runtime.h>
#include <cstdint>

// YOLO v1 loss: S=7, NB=2, C=20. predictions [N, 7*7*30], targets [N,7,7,25].
// Persistent warps, double-buffered cp.async staging: each warp grid-strides
// over 32-cell chunks, prefetching chunk k+1 (stage buffer B) while computing
// chunk k (stage buffer A). Single kernel; last CTA publishes the scalar.

#define S_ 7
#define C_ 20
#define CELL_PRED 30   // C + NB*5
#define CELL_TGT  25   // C + 5
#define LAMBDA_COORD 5.0f
#define LAMBDA_NOOBJ 0.5f
#define EPS_ 1e-6f

#define TPB 256
#define WARPS (TPB / 32)
#define CHUNK 32                      // cells per chunk (one per lane)
#define CHUNK_PRED_F4 (CHUNK * CELL_PRED / 4)   // 240
#define CHUNK_TGT_F4  (CHUNK * CELL_TGT / 4)    // 200
#define STAGE_F (CHUNK * (CELL_PRED + CELL_TGT))  // 1760 floats = 7040 B
#define SMEM_BYTES (WARPS * 2 * STAGE_F * 4)      // 112640 B

__device__ float        g_partial;   // zero-initialized at module load
__device__ unsigned int g_count;

__device__ __forceinline__ void cp16(unsigned int smem_dst, const void* gmem_src) {
    asm volatile("cp.async.cg.shared.global [%0], [%1], 16;"
                 :: "r"(smem_dst), "l"(gmem_src));
}
__device__ __forceinline__ void cp_commit() {
    asm volatile("cp.async.commit_group;");
}
__device__ __forceinline__ void cp_wait1() {
    asm volatile("cp.async.wait_group 1;" ::: "memory");
}
__device__ __forceinline__ void cp_wait0() {
    asm volatile("cp.async.wait_group 0;" ::: "memory");
}

__device__ __forceinline__ float iou_mid(const float* a, const float* b) {
    float ax1 = a[0] - a[2] * 0.5f, ay1 = a[1] - a[3] * 0.5f;
    float ax2 = a[0] + a[2] * 0.5f, ay2 = a[1] + a[3] * 0.5f;
    float bx1 = b[0] - b[2] * 0.5f, by1 = b[1] - b[3] * 0.5f;
    float bx2 = b[0] + b[2] * 0.5f, by2 = b[1] + b[3] * 0.5f;
    float iw = fmaxf(fminf(ax2, bx2) - fmaxf(ax1, bx1), 0.0f);
    float ih = fmaxf(fminf(ay2, by2) - fmaxf(ay1, by1), 0.0f);
    float inter  = iw * ih;
    float area_a = fabsf((ax2 - ax1) * (ay2 - ay1));
    float area_b = fabsf((bx2 - bx1) * (by2 - by1));
    return inter / (area_a + area_b - inter + EPS_);
}

// Stage chunk c (if c < nch) into the stage buffer; always commits a group.
__device__ __forceinline__ void stage_chunk(
    int c, int nch, int total_cells, int lane,
    const float* __restrict__ pred, const float* __restrict__ tgt,
    float* wp, float* wt, unsigned int wp_addr, unsigned int wt_addr)
{
    if (c < nch) {
        const int cell0 = c * CHUNK;
        const int cells = min(CHUNK, total_cells - cell0);
        const float4* gp = reinterpret_cast<const float4*>(pred + (size_t)cell0 * CELL_PRED);
        const float4* gt = reinterpret_cast<const float4*>(tgt  + (size_t)cell0 * CELL_TGT);
        if (cells == CHUNK) {
            #pragma unroll
            for (int i = 0; i < 8; i++) {
                int idx = lane + i * 32;
                if (idx < CHUNK_PRED_F4) cp16(wp_addr + idx * 16, gp + idx);
            }
            #pragma unroll
            for (int i = 0; i < 7; i++) {
                int idx = lane + i * 32;
                if (idx < CHUNK_TGT_F4) cp16(wt_addr + idx * 16, gt + idx);
            }
        } else {
            // partial tail chunk: cp.async full f4s, scalar for the remainder
            int pf = cells * CELL_PRED;        // valid floats
            int tf = cells * CELL_TGT;
            for (int idx = lane; idx * 4 + 4 <= pf; idx += 32) cp16(wp_addr + idx * 16, gp + idx);
            for (int idx = lane; idx * 4 + 4 <= tf; idx += 32) cp16(wt_addr + idx * 16, gt + idx);
            const float* gps = pred + (size_t)cell0 * CELL_PRED;
            const float* gts = tgt  + (size_t)cell0 * CELL_TGT;
            for (int i = (pf & ~3) + lane; i < pf; i += 32) wp[i] = __ldg(gps + i);
            for (int i = (tf & ~3) + lane; i < tf; i += 32) wt[i] = __ldg(gts + i);
        }
    }
    cp_commit();
}

__global__ __launch_bounds__(TPB) void yolo_loss_kernel(
    const float* __restrict__ pred,
    const float* __restrict__ tgt,
    float* __restrict__ out,
    int total_cells,
    float invN)
{
    extern __shared__ float smem[];               // WARPS * 2 * STAGE_F floats
    __shared__ float warp_sums[WARPS];

    const int lane = threadIdx.x & 31;
    const int wid  = threadIdx.x >> 5;

    const int gwarp = blockIdx.x * WARPS + wid;   // global warp id
    const int wstride = gridDim.x * WARPS;
    const int nch = (total_cells + CHUNK - 1) / CHUNK;

    float* base = smem + wid * (2 * STAGE_F);
    float* wp[2] = { base,               base + STAGE_F };
    float* wt[2] = { base + CHUNK * CELL_PRED, base + STAGE_F + CHUNK * CELL_PRED };
    unsigned int wpa[2], wta[2];
    #pragma unroll
    for (int s = 0; s < 2; s++) {
        wpa[s] = (unsigned int)__cvta_generic_to_shared(wp[s]);
        wta[s] = (unsigned int)__cvta_generic_to_shared(wt[s]);
    }

    // Prologue: prefetch first two chunks
    stage_chunk(gwarp,           nch, total_cells, lane, pred, tgt, wp[0], wt[0], wpa[0], wta[0]);
    stage_chunk(gwarp + wstride, nch, total_cells, lane, pred, tgt, wp[1], wt[1], wpa[1], wta[1]);

    float acc = 0.0f;
    int buf = 0;
    for (int k = gwarp; k < nch; k += wstride, buf ^= 1) {
        cp_wait1();                               // oldest group (chunk k) done
        __syncwarp();

        const int cell = k * CHUNK + lane;
        if (cell < total_cells) {
            const float* p = wp[buf] + lane * CELL_PRED;
            const float* t = wt[buf] + lane * CELL_TGT;

            float cls = 0.0f;
            #pragma unroll
            for (int c = 0; c < C_; c++) {
                float d = p[c] - t[c];
                cls = fmaf(d, d, cls);
            }

            bool obj = (t[C_] == 1.0f);

            float i1 = iou_mid(p + C_,     t + C_);
            float i2 = iou_mid(p + C_ + 5, t + C_);
            const float* r = (i1 > i2) ? (p + C_) : (p + C_ + 5);

            float dx = r[0] - t[C_ + 0];
            float dy = r[1] - t[C_ + 1];
            float xy = fmaf(dx, dx, dy * dy);
            float dw = sqrtf(r[2]) - sqrtf(t[C_ + 2]);
            float dh = sqrtf(r[3]) - sqrtf(t[C_ + 3]);
            float wh = fmaf(dw, dw, dh * dh);
            float coord = LAMBDA_COORD * (xy + wh);
            float dc = r[4] - t[C_ + 4];
            float conf = dc * dc;

            float c1 = p[C_ + 4];
            float c2 = p[C_ + 9];
            float noobj = LAMBDA_NOOBJ * fmaf(c1, c1, c2 * c2);

            acc += obj ? (coord + conf + cls) : noobj;
        }

        __syncwarp();                             // all lanes done reading buf
        stage_chunk(k + 2 * wstride, nch, total_cells, lane, pred, tgt,
                    wp[buf], wt[buf], wpa[buf], wta[buf]);
    }
    cp_wait0();

    acc *= invN;

    // warp reduce
    #pragma unroll
    for (int off = 16; off > 0; off >>= 1)
        acc += __shfl_down_sync(0xFFFFFFFFu, acc, off);
    if (lane == 0) warp_sums[wid] = acc;
    __syncthreads();

    if (wid == 0) {
        float s = (lane < WARPS) ? warp_sums[lane] : 0.0f;
        #pragma unroll
        for (int off = 4; off > 0; off >>= 1)
            s += __shfl_down_sync(0xFFFFFFFFu, s, off);
        if (lane == 0) {
            atomicAdd(&g_partial, s);
            __threadfence();
            unsigned int done = atomicAdd(&g_count, 1u);
            if (done == gridDim.x - 1) {          // last CTA publishes + resets
                out[0] = g_partial;
                g_partial = 0.0f;
                g_count = 0u;
                __threadfence();
            }
        }
    }
}

extern "C" void kernel_launch(void* const* d_in, const int* in_sizes, int n_in,
                              void* d_out, int out_size)
{
    const float* pred = (const float*)d_in[0];
    const float* tgt  = (const float*)d_in[1];
    float* out = (float*)d_out;

    int N = in_sizes[0] / (S_ * S_ * (C_ + 10));
    int total_cells = N * S_ * S_;
    float invN = 1.0f / (float)N;

    static bool attr_set = false;
    if (!attr_set) {
        cudaFuncSetAttribute(yolo_loss_kernel,
                             cudaFuncAttributeMaxDynamicSharedMemorySize, SMEM_BYTES);
        attr_set = true;
    }

    int nch = (total_cells + CHUNK - 1) / CHUNK;
    int blocks_needed = (nch + WARPS - 1) / WARPS;
    int blocks = blocks_needed < 296 ? blocks_needed : 296;   // 2 CTAs/SM, 1 wave

    yolo_loss_kernel<<<blocks, TPB, SMEM_BYTES>>>(pred, tgt, out, total_cells, invN);
}